// round 2
// baseline (speedup 1.0000x reference)
#include <cuda_runtime.h>

#define BATCH 64
#define SEQ   512
#define HID   1024
#define LBL   5

// Scratch (no allocations allowed -> __device__ globals)
__device__ float g_emis[BATCH * SEQ * LBL];   // relu(feats@W+b), [B,S,L]
__device__ float g_res[BATCH];                // per-batch (numerator - log_z)

// ---------------------------------------------------------------------------
// Kernel 1: emissions = relu(feats @ W_tag + b_tag)
// One warp per row (row = b*SEQ + t). 32 warps/block. W transposed in shared
// as [j][k] so float4 LDS is conflict-free. HBM-bound by feats traffic.
// ---------------------------------------------------------------------------
__global__ __launch_bounds__(1024) void emis_kernel(
    const float* __restrict__ feats,   // [B*S, HID]
    const float* __restrict__ W,       // [HID, LBL]
    const float* __restrict__ bias)    // [LBL]
{
    __shared__ float sW[LBL * HID];    // transposed: sW[j*HID + k]
    int tid = threadIdx.x;
    for (int idx = tid; idx < LBL * HID; idx += 1024) {
        int k = idx / LBL, j = idx - k * LBL;
        sW[j * HID + k] = W[idx];
    }
    __syncthreads();

    int warp = tid >> 5, lane = tid & 31;
    int row = blockIdx.x * 32 + warp;

    const float4* f4 = reinterpret_cast<const float4*>(feats) + (size_t)row * (HID / 4);
    const float4* w4 = reinterpret_cast<const float4*>(sW);

    float acc0 = 0.f, acc1 = 0.f, acc2 = 0.f, acc3 = 0.f, acc4 = 0.f;
#pragma unroll
    for (int i = 0; i < HID / 4 / 32; i++) {
        int k4 = lane + 32 * i;
        float4 f = f4[k4];
        float4 w;
        w = w4[0 * (HID / 4) + k4]; acc0 += f.x * w.x + f.y * w.y + f.z * w.z + f.w * w.w;
        w = w4[1 * (HID / 4) + k4]; acc1 += f.x * w.x + f.y * w.y + f.z * w.z + f.w * w.w;
        w = w4[2 * (HID / 4) + k4]; acc2 += f.x * w.x + f.y * w.y + f.z * w.z + f.w * w.w;
        w = w4[3 * (HID / 4) + k4]; acc3 += f.x * w.x + f.y * w.y + f.z * w.z + f.w * w.w;
        w = w4[4 * (HID / 4) + k4]; acc4 += f.x * w.x + f.y * w.y + f.z * w.z + f.w * w.w;
    }
#pragma unroll
    for (int off = 16; off; off >>= 1) {
        acc0 += __shfl_down_sync(0xffffffffu, acc0, off);
        acc1 += __shfl_down_sync(0xffffffffu, acc1, off);
        acc2 += __shfl_down_sync(0xffffffffu, acc2, off);
        acc3 += __shfl_down_sync(0xffffffffu, acc3, off);
        acc4 += __shfl_down_sync(0xffffffffu, acc4, off);
    }
    if (lane == 0) {
        float* o = g_emis + (size_t)row * LBL;
        o[0] = fmaxf(acc0 + bias[0], 0.f);
        o[1] = fmaxf(acc1 + bias[1], 0.f);
        o[2] = fmaxf(acc2 + bias[2], 0.f);
        o[3] = fmaxf(acc3 + bias[3], 0.f);
        o[4] = fmaxf(acc4 + bias[4], 0.f);
    }
}

// ---------------------------------------------------------------------------
// Kernel 2: per-batch CRF forward (log_z) + Viterbi (+backtrace) + numerator.
// One block per batch: warp 0 runs the sequential scan (lanes 0..4 carry
// alpha[j], v[j]); warps 1..3 compute the gold-path numerator concurrently.
// ---------------------------------------------------------------------------
__global__ __launch_bounds__(128) void crf_kernel(
    const int*   __restrict__ labels,       // [B, S]
    const float* __restrict__ start_trans,  // [L]
    const float* __restrict__ end_trans,    // [L]
    const float* __restrict__ trans,        // [L, L] row-major (prev, cur)
    const float* __restrict__ weights,      // [L]
    float*       __restrict__ out_paths)    // d_out + 1, [B, S]
{
    __shared__ float         s_e[SEQ * LBL];          // emissions for this batch
    __shared__ unsigned char s_bp[(SEQ - 1) * LBL];   // backpointers
    __shared__ unsigned char s_path[SEQ];
    __shared__ float         s_logz;
    __shared__ float         s_numpart[4];

    int b = blockIdx.x;
    int tid = threadIdx.x, warp = tid >> 5, lane = tid & 31;

    // Stage this batch's emissions into shared (coalesced; resident in L2)
    const float* eb = g_emis + (size_t)b * SEQ * LBL;
    for (int i = tid; i < SEQ * LBL; i += 128) s_e[i] = eb[i];
    __syncthreads();

    if (warp == 0) {
        // ------- sequential forward + viterbi scan -------
        bool act = lane < LBL;
        int j = act ? lane : 0;
        float Tc0 = trans[0 * LBL + j];
        float Tc1 = trans[1 * LBL + j];
        float Tc2 = trans[2 * LBL + j];
        float Tc3 = trans[3 * LBL + j];
        float Tc4 = trans[4 * LBL + j];
        float en  = end_trans[j];

        float alpha = start_trans[j] + s_e[j];
        float v = alpha;
        float e_next = s_e[LBL + j];   // prefetched emission for t=1

        for (int t = 1; t < SEQ; t++) {
            float e = e_next;
            if (t + 1 < SEQ) e_next = s_e[(t + 1) * LBL + j];  // off critical path

            float a0 = __shfl_sync(0xffffffffu, alpha, 0);
            float a1 = __shfl_sync(0xffffffffu, alpha, 1);
            float a2 = __shfl_sync(0xffffffffu, alpha, 2);
            float a3 = __shfl_sync(0xffffffffu, alpha, 3);
            float a4 = __shfl_sync(0xffffffffu, alpha, 4);
            float v0 = __shfl_sync(0xffffffffu, v, 0);
            float v1 = __shfl_sync(0xffffffffu, v, 1);
            float v2 = __shfl_sync(0xffffffffu, v, 2);
            float v3 = __shfl_sync(0xffffffffu, v, 3);
            float v4 = __shfl_sync(0xffffffffu, v, 4);

            // forward: logsumexp over prev states
            float x0 = a0 + Tc0, x1 = a1 + Tc1, x2 = a2 + Tc2, x3 = a3 + Tc3, x4 = a4 + Tc4;
            float m = fmaxf(fmaxf(fmaxf(x0, x1), fmaxf(x2, x3)), x4);
            float me = m + e;  // hoisted off the exp/log chain
            float s = (__expf(x0 - m) + __expf(x1 - m))
                    + (__expf(x2 - m) + __expf(x3 - m)) + __expf(x4 - m);
            float nalpha = me + __logf(s);

            // viterbi: max + argmax (first-occurrence on ties, like jnp.argmax)
            float y0 = v0 + Tc0, y1 = v1 + Tc1, y2 = v2 + Tc2, y3 = v3 + Tc3, y4 = v4 + Tc4;
            float best = y0; int idx = 0;
            if (y1 > best) { best = y1; idx = 1; }
            if (y2 > best) { best = y2; idx = 2; }
            if (y3 > best) { best = y3; idx = 3; }
            if (y4 > best) { best = y4; idx = 4; }
            float nv = best + e;

            alpha = nalpha;
            v = nv;
            if (act) s_bp[(t - 1) * LBL + j] = (unsigned char)idx;
        }

        // log_z = logsumexp(alpha + end)
        float z = alpha + en;
        float z0 = __shfl_sync(0xffffffffu, z, 0);
        float z1 = __shfl_sync(0xffffffffu, z, 1);
        float z2 = __shfl_sync(0xffffffffu, z, 2);
        float z3 = __shfl_sync(0xffffffffu, z, 3);
        float z4 = __shfl_sync(0xffffffffu, z, 4);
        float mz = fmaxf(fmaxf(fmaxf(z0, z1), fmaxf(z2, z3)), z4);
        float sz = __expf(z0 - mz) + __expf(z1 - mz) + __expf(z2 - mz)
                 + __expf(z3 - mz) + __expf(z4 - mz);
        float logz = mz + __logf(sz);

        // last = argmax(v + end)
        float f = v + en;
        float f0 = __shfl_sync(0xffffffffu, f, 0);
        float f1 = __shfl_sync(0xffffffffu, f, 1);
        float f2 = __shfl_sync(0xffffffffu, f, 2);
        float f3 = __shfl_sync(0xffffffffu, f, 3);
        float f4 = __shfl_sync(0xffffffffu, f, 4);
        float fb = f0; int last = 0;
        if (f1 > fb) { fb = f1; last = 1; }
        if (f2 > fb) { fb = f2; last = 2; }
        if (f3 > fb) { fb = f3; last = 3; }
        if (f4 > fb) { fb = f4; last = 4; }

        __syncwarp();  // make s_bp writes visible to lane 0
        if (lane == 0) {
            s_logz = logz;
            int cur = last;
            s_path[SEQ - 1] = (unsigned char)cur;
            for (int k = SEQ - 2; k >= 0; k--) {
                cur = s_bp[k * LBL + cur];
                s_path[k] = (unsigned char)cur;
            }
        }
    } else {
        // ------- numerator partial sums (warps 1..3: 96 threads over t) -------
        const int* lb = labels + b * SEQ;
        float acc = 0.f;
        for (int t = tid - 32; t < SEQ; t += 96) {
            int l = lb[t];
            acc += weights[l] * s_e[t * LBL + l];
            if (t + 1 < SEQ) acc += trans[l * LBL + lb[t + 1]];
        }
#pragma unroll
        for (int off = 16; off; off >>= 1)
            acc += __shfl_down_sync(0xffffffffu, acc, off);
        if (lane == 0) s_numpart[warp] = acc;
    }
    __syncthreads();

    if (tid == 0) {
        const int* lb = labels + b * SEQ;
        float num = start_trans[lb[0]] + end_trans[lb[SEQ - 1]]
                  + s_numpart[1] + s_numpart[2] + s_numpart[3];
        g_res[b] = num - s_logz;
    }

    // write decoded paths (as float, per output dtype)
    for (int t = tid; t < SEQ; t += 128)
        out_paths[(size_t)b * SEQ + t] = (float)s_path[t];
}

// ---------------------------------------------------------------------------
// Kernel 3: loss = -sum_b (num - logz) / (B*S)
// ---------------------------------------------------------------------------
__global__ void finalize_kernel(float* __restrict__ d_out)
{
    int lane = threadIdx.x;
    float acc = g_res[lane] + g_res[lane + 32];
#pragma unroll
    for (int off = 16; off; off >>= 1)
        acc += __shfl_down_sync(0xffffffffu, acc, off);
    if (lane == 0)
        d_out[0] = -acc / (float)(BATCH * SEQ);
}

// ---------------------------------------------------------------------------
extern "C" void kernel_launch(void* const* d_in, const int* in_sizes, int n_in,
                              void* d_out, int out_size)
{
    const float* feats       = (const float*)d_in[0];  // [B,S,H]
    const int*   labels      = (const int*)  d_in[1];  // [B,S]
    // d_in[2] = mask: all-ones by construction, ignored
    const float* W_tag       = (const float*)d_in[3];  // [H,L]
    const float* b_tag       = (const float*)d_in[4];  // [L]
    const float* start_trans = (const float*)d_in[5];  // [L]
    const float* end_trans   = (const float*)d_in[6];  // [L]
    const float* trans       = (const float*)d_in[7];  // [L,L]
    const float* weights     = (const float*)d_in[8];  // [L]

    float* out = (float*)d_out;  // [0] = loss, [1..B*S] = paths

    emis_kernel<<<(BATCH * SEQ) / 32, 1024>>>(feats, W_tag, b_tag);
    crf_kernel<<<BATCH, 128>>>(labels, start_trans, end_trans, trans, weights, out + 1);
    finalize_kernel<<<1, 32>>>(out);
}

// round 3
// speedup vs baseline: 1.6055x; 1.6055x over previous
#include <cuda_runtime.h>

#define BATCH 64
#define SEQ   512
#define HID   1024
#define LBL   5

// Scratch (no allocations allowed -> __device__ globals)
__device__ float g_emis[BATCH * SEQ * LBL];   // relu(feats@W+b), [B,S,L]
__device__ float g_res[BATCH];                // per-batch (numerator - log_z)
__device__ int   g_cnt = 0;                   // last-block election counter

// ---------------------------------------------------------------------------
// Kernel 1: emissions = relu(feats @ W_tag + b_tag)
// 4 rows per warp: 5 LDS.128 of W amortized over 4 LDG.128 of feats
// -> LSU/L1 traffic per DRAM byte cut 4x vs 1-row version. DRAM-bound target.
// ---------------------------------------------------------------------------
__global__ __launch_bounds__(512) void emis_kernel(
    const float* __restrict__ feats,   // [B*S, HID]
    const float* __restrict__ W,       // [HID, LBL]
    const float* __restrict__ bias)    // [LBL]
{
    __shared__ float sW[LBL * HID];    // transposed: sW[j*HID + k]
    int tid = threadIdx.x;
    for (int idx = tid; idx < LBL * HID; idx += 512) {
        int k = idx / LBL, j = idx - k * LBL;
        sW[j * HID + k] = W[idx];
    }
    __syncthreads();

    int warp = tid >> 5, lane = tid & 31;
    int row0 = blockIdx.x * 64 + warp * 4;   // 16 warps * 4 rows = 64 rows/block

    const float4* w4 = reinterpret_cast<const float4*>(sW);
    const float4* f4 = reinterpret_cast<const float4*>(feats) + (size_t)row0 * (HID / 4);

    float acc[4][LBL];
#pragma unroll
    for (int r = 0; r < 4; r++)
#pragma unroll
        for (int j = 0; j < LBL; j++) acc[r][j] = 0.f;

#pragma unroll
    for (int i = 0; i < HID / 4 / 32; i++) {
        int k4 = lane + 32 * i;
        float4 f[4];
#pragma unroll
        for (int r = 0; r < 4; r++) f[r] = f4[(size_t)r * (HID / 4) + k4];
#pragma unroll
        for (int j = 0; j < LBL; j++) {
            float4 w = w4[j * (HID / 4) + k4];
#pragma unroll
            for (int r = 0; r < 4; r++)
                acc[r][j] += f[r].x * w.x + f[r].y * w.y + f[r].z * w.z + f[r].w * w.w;
        }
    }

#pragma unroll
    for (int r = 0; r < 4; r++)
#pragma unroll
        for (int j = 0; j < LBL; j++)
#pragma unroll
            for (int off = 16; off; off >>= 1)
                acc[r][j] += __shfl_down_sync(0xffffffffu, acc[r][j], off);

    if (lane == 0) {
#pragma unroll
        for (int r = 0; r < 4; r++) {
            float* o = g_emis + (size_t)(row0 + r) * LBL;
#pragma unroll
            for (int j = 0; j < LBL; j++)
                o[j] = fmaxf(acc[r][j] + bias[j], 0.f);
        }
    }
}

// ---------------------------------------------------------------------------
// Kernel 2: per-batch CRF. One block per batch, 10 warps:
//   warp 0   : sequential Viterbi scan (lanes 0-4), backpointers -> smem
//   warp 1   : gold-path numerator
//   warps 2-9: forward logsumexp as 8 chunk operators (5x5 log-semiring),
//              composed by warp 2 after a named barrier -> log_z
// Then: pointer-jumping backtrace (exact integer map composition, 9 levels),
// path write, and last-block loss reduction (deterministic fixed-order sum).
// ---------------------------------------------------------------------------
__global__ __launch_bounds__(320) void crf_kernel(
    const int*   __restrict__ labels,       // [B, S]
    const float* __restrict__ start_trans,  // [L]
    const float* __restrict__ end_trans,    // [L]
    const float* __restrict__ trans,        // [L, L] (prev, cur)
    const float* __restrict__ weights,      // [L]
    float*       __restrict__ d_out)        // [0]=loss, [1..]=paths
{
    __shared__ float         s_e[SEQ * LBL];        // emissions, this batch
    __shared__ unsigned char s_F[2][SEQ * LBL];     // map buffers (row 511 = identity)
    __shared__ float         s_M[8][25];            // chunk operators
    __shared__ float         s_logz, s_num;
    __shared__ int           s_last;

    int b = blockIdx.x;
    int tid = threadIdx.x, warp = tid >> 5, lane = tid & 31;

    const float* eb = g_emis + (size_t)b * SEQ * LBL;
    for (int i = tid; i < SEQ * LBL; i += 320) s_e[i] = eb[i];
    __syncthreads();

    if (warp == 0) {
        // ---------------- Viterbi (sequential, lanes 0-4) ----------------
        bool act = lane < LBL;
        int j = act ? lane : 0;
        float Tc0 = trans[0 * LBL + j];
        float Tc1 = trans[1 * LBL + j];
        float Tc2 = trans[2 * LBL + j];
        float Tc3 = trans[3 * LBL + j];
        float Tc4 = trans[4 * LBL + j];
        float en  = end_trans[j];

        float v = start_trans[j] + s_e[j];
        float e_next = s_e[LBL + j];

        for (int t = 1; t < SEQ; t++) {
            float e = e_next;
            if (t + 1 < SEQ) e_next = s_e[(t + 1) * LBL + j];

            float v0 = __shfl_sync(0xffffffffu, v, 0);
            float v1 = __shfl_sync(0xffffffffu, v, 1);
            float v2 = __shfl_sync(0xffffffffu, v, 2);
            float v3 = __shfl_sync(0xffffffffu, v, 3);
            float v4 = __shfl_sync(0xffffffffu, v, 4);

            float y0 = v0 + Tc0, y1 = v1 + Tc1, y2 = v2 + Tc2,
                  y3 = v3 + Tc3, y4 = v4 + Tc4;
            float best = y0; int idx = 0;
            if (y1 > best) { best = y1; idx = 1; }
            if (y2 > best) { best = y2; idx = 2; }
            if (y3 > best) { best = y3; idx = 3; }
            if (y4 > best) { best = y4; idx = 4; }
            v = best + e;
            if (act) s_F[0][(t - 1) * LBL + j] = (unsigned char)idx;
        }

        // last = argmax(v + end), first index wins ties
        float f = v + en;
        float f0 = __shfl_sync(0xffffffffu, f, 0);
        float f1 = __shfl_sync(0xffffffffu, f, 1);
        float f2 = __shfl_sync(0xffffffffu, f, 2);
        float f3 = __shfl_sync(0xffffffffu, f, 3);
        float f4 = __shfl_sync(0xffffffffu, f, 4);
        float fb = f0; int last = 0;
        if (f1 > fb) { fb = f1; last = 1; }
        if (f2 > fb) { fb = f2; last = 2; }
        if (f3 > fb) { fb = f3; last = 3; }
        if (f4 > fb) { fb = f4; last = 4; }
        if (lane == 0) s_last = last;
        if (act) s_F[0][(SEQ - 1) * LBL + j] = (unsigned char)j;  // identity row
    } else if (warp == 1) {
        // ---------------- numerator ----------------
        const int* lb = labels + b * SEQ;
        float acc = 0.f;
        for (int t = lane; t < SEQ; t += 32) {
            int l = lb[t];
            acc += weights[l] * s_e[t * LBL + l];
            if (t + 1 < SEQ) acc += trans[l * LBL + lb[t + 1]];
        }
#pragma unroll
        for (int off = 16; off; off >>= 1)
            acc += __shfl_down_sync(0xffffffffu, acc, off);
        if (lane == 0)
            s_num = acc + start_trans[lb[0]] + end_trans[lb[SEQ - 1]];
    } else {
        // ---------------- forward chunks (warps 2..9, chunk c = warp-2) ----
        int c = warp - 2;
        int t0 = (c == 0) ? 1 : 64 * c;
        int t1 = 64 * c + 63;
        bool act = lane < 25;
        int p = act ? lane : 0;
        int i5 = (p / 5) * 5;       // base lane of my source row
        int jj = p % 5;

        float Tr0 = trans[0 * LBL + jj];
        float Tr1 = trans[1 * LBL + jj];
        float Tr2 = trans[2 * LBL + jj];
        float Tr3 = trans[3 * LBL + jj];
        float Tr4 = trans[4 * LBL + jj];

        // M = A_{t0}
        float M = trans[(p / 5) * LBL + jj] + s_e[t0 * LBL + jj];

        for (int t = t0 + 1; t <= t1; t++) {
            float e = s_e[t * LBL + jj];
            float m0 = __shfl_sync(0xffffffffu, M, i5 + 0);
            float m1 = __shfl_sync(0xffffffffu, M, i5 + 1);
            float m2 = __shfl_sync(0xffffffffu, M, i5 + 2);
            float m3 = __shfl_sync(0xffffffffu, M, i5 + 3);
            float m4 = __shfl_sync(0xffffffffu, M, i5 + 4);
            float x0 = m0 + Tr0, x1 = m1 + Tr1, x2 = m2 + Tr2,
                  x3 = m3 + Tr3, x4 = m4 + Tr4;
            float mm = fmaxf(fmaxf(fmaxf(x0, x1), fmaxf(x2, x3)), x4);
            float me = mm + e;
            float s = (__expf(x0 - mm) + __expf(x1 - mm))
                    + (__expf(x2 - mm) + __expf(x3 - mm)) + __expf(x4 - mm);
            M = me + __logf(s);
        }
        if (act) s_M[c][p] = M;

        asm volatile("bar.sync 1, 256;" ::: "memory");  // warps 2..9 only

        if (warp == 2) {
            // compose: alpha0 (x) M_0 (x) ... (x) M_7, then log_z
            int j = (lane < LBL) ? lane : 0;
            float al = start_trans[j] + s_e[j];
#pragma unroll
            for (int cc = 0; cc < 8; cc++) {
                float a0 = __shfl_sync(0xffffffffu, al, 0);
                float a1 = __shfl_sync(0xffffffffu, al, 1);
                float a2 = __shfl_sync(0xffffffffu, al, 2);
                float a3 = __shfl_sync(0xffffffffu, al, 3);
                float a4 = __shfl_sync(0xffffffffu, al, 4);
                float x0 = a0 + s_M[cc][0 * 5 + j];
                float x1 = a1 + s_M[cc][1 * 5 + j];
                float x2 = a2 + s_M[cc][2 * 5 + j];
                float x3 = a3 + s_M[cc][3 * 5 + j];
                float x4 = a4 + s_M[cc][4 * 5 + j];
                float mm = fmaxf(fmaxf(fmaxf(x0, x1), fmaxf(x2, x3)), x4);
                float s = (__expf(x0 - mm) + __expf(x1 - mm))
                        + (__expf(x2 - mm) + __expf(x3 - mm)) + __expf(x4 - mm);
                al = mm + __logf(s);
            }
            float z = al + end_trans[j];
            float z0 = __shfl_sync(0xffffffffu, z, 0);
            float z1 = __shfl_sync(0xffffffffu, z, 1);
            float z2 = __shfl_sync(0xffffffffu, z, 2);
            float z3 = __shfl_sync(0xffffffffu, z, 3);
            float z4 = __shfl_sync(0xffffffffu, z, 4);
            float mz = fmaxf(fmaxf(fmaxf(z0, z1), fmaxf(z2, z3)), z4);
            float sz = __expf(z0 - mz) + __expf(z1 - mz) + __expf(z2 - mz)
                     + __expf(z3 - mz) + __expf(z4 - mz);
            if (lane == 0) s_logz = mz + __logf(sz);
        }
    }
    __syncthreads();

    // per-batch result + last-block deterministic loss reduction
    if (tid == 0) {
        g_res[b] = s_num - s_logz;
        __threadfence();
        int done = atomicAdd(&g_cnt, 1);
        if (done == BATCH - 1) {
            __threadfence();
            float a = 0.f;
            for (int q = 0; q < BATCH; q++) a += g_res[q];
            d_out[0] = -a / (float)(BATCH * SEQ);
            g_cnt = 0;  // reset for next graph replay
        }
    }

    // ---------------- pointer-jumping backtrace (exact) ----------------
    // s_F[src] row t in [0,510] = bp map (tag_{t+1} -> tag_t); row 511 = id.
    int src = 0;
    for (int d = 1; d < SEQ; d <<= 1) {
        int dst = src ^ 1;
        for (int t = tid; t < SEQ; t += 320) {
            unsigned char f[LBL];
            if (t + d <= SEQ - 1) {
#pragma unroll
                for (int q = 0; q < LBL; q++)
                    f[q] = s_F[src][t * LBL + s_F[src][(t + d) * LBL + q]];
            } else {
#pragma unroll
                for (int q = 0; q < LBL; q++)
                    f[q] = s_F[src][t * LBL + q];
            }
#pragma unroll
            for (int q = 0; q < LBL; q++)
                s_F[dst][t * LBL + q] = f[q];
        }
        __syncthreads();
        src ^= 1;
    }

    int last = s_last;
    float* out_paths = d_out + 1;
    for (int t = tid; t < SEQ; t += 320) {
        int tag = (t == SEQ - 1) ? last : (int)s_F[src][t * LBL + last];
        out_paths[(size_t)b * SEQ + t] = (float)tag;
    }
}

// ---------------------------------------------------------------------------
extern "C" void kernel_launch(void* const* d_in, const int* in_sizes, int n_in,
                              void* d_out, int out_size)
{
    const float* feats       = (const float*)d_in[0];  // [B,S,H]
    const int*   labels      = (const int*)  d_in[1];  // [B,S]
    // d_in[2] = mask: all-ones by construction, ignored
    const float* W_tag       = (const float*)d_in[3];  // [H,L]
    const float* b_tag       = (const float*)d_in[4];  // [L]
    const float* start_trans = (const float*)d_in[5];  // [L]
    const float* end_trans   = (const float*)d_in[6];  // [L]
    const float* trans       = (const float*)d_in[7];  // [L,L]
    const float* weights     = (const float*)d_in[8];  // [L]

    float* out = (float*)d_out;  // [0] = loss, [1..B*S] = paths

    emis_kernel<<<(BATCH * SEQ) / 64, 512>>>(feats, W_tag, b_tag);
    crf_kernel<<<BATCH, 320>>>(labels, start_trans, end_trans, trans, weights, out);
}

// round 4
// speedup vs baseline: 1.6103x; 1.0030x over previous
#include <cuda_runtime.h>

#define BATCH 64
#define SEQ   512
#define HID   1024
#define LBL   5

// Scratch (no allocations allowed -> __device__ globals)
__device__ float g_emis[BATCH * SEQ * LBL];   // relu(feats@W+b), [B,S,L]
__device__ float g_res[BATCH];                // per-batch (numerator - log_z)
__device__ int   g_cnt = 0;                   // last-block election counter

// ---------------------------------------------------------------------------
// Kernel 1: emissions = relu(feats @ W_tag + b_tag)
// 8 rows per warp, 256-thread blocks (8 warps, 64 rows/block, grid=512).
// 5 LDS.128 of W amortized over 8 LDG.128 of feats -> L1 no longer binding;
// target DRAM-bound (~16us floor on 128MB feats).
// ---------------------------------------------------------------------------
__global__ __launch_bounds__(256) void emis_kernel(
    const float* __restrict__ feats,   // [B*S, HID]
    const float* __restrict__ W,       // [HID, LBL]
    const float* __restrict__ bias)    // [LBL]
{
    __shared__ float sW[LBL * HID];    // transposed: sW[j*HID + k]
    int tid = threadIdx.x;
    for (int idx = tid; idx < LBL * HID; idx += 256) {
        int k = idx / LBL, j = idx - k * LBL;
        sW[j * HID + k] = W[idx];
    }
    __syncthreads();

    int warp = tid >> 5, lane = tid & 31;
    int row0 = blockIdx.x * 64 + warp * 8;   // 8 warps * 8 rows = 64 rows/block

    const float4* w4 = reinterpret_cast<const float4*>(sW);
    const float4* f4 = reinterpret_cast<const float4*>(feats) + (size_t)row0 * (HID / 4);

    float acc[8][LBL];
#pragma unroll
    for (int r = 0; r < 8; r++)
#pragma unroll
        for (int j = 0; j < LBL; j++) acc[r][j] = 0.f;

#pragma unroll
    for (int i = 0; i < HID / 4 / 32; i++) {
        int k4 = lane + 32 * i;
        float4 f[8];
#pragma unroll
        for (int r = 0; r < 8; r++) f[r] = f4[(size_t)r * (HID / 4) + k4];
#pragma unroll
        for (int j = 0; j < LBL; j++) {
            float4 w = w4[j * (HID / 4) + k4];
#pragma unroll
            for (int r = 0; r < 8; r++)
                acc[r][j] += f[r].x * w.x + f[r].y * w.y + f[r].z * w.z + f[r].w * w.w;
        }
    }

#pragma unroll
    for (int r = 0; r < 8; r++)
#pragma unroll
        for (int j = 0; j < LBL; j++)
#pragma unroll
            for (int off = 16; off; off >>= 1)
                acc[r][j] += __shfl_down_sync(0xffffffffu, acc[r][j], off);

    if (lane == 0) {
#pragma unroll
        for (int r = 0; r < 8; r++) {
            float* o = g_emis + (size_t)(row0 + r) * LBL;
#pragma unroll
            for (int j = 0; j < LBL; j++)
                o[j] = fmaxf(acc[r][j] + bias[j], 0.f);
        }
    }
}

// ---------------------------------------------------------------------------
// Kernel 2: per-batch CRF. One block per batch, 10 warps:
//   warp 0   : sequential Viterbi scan (lanes 0-4). Value path = balanced
//              FMNMX tree (bit-exact: max is associative); argmax index via
//              SELs OFF the dependency chain (tie -> first index, like jnp).
//   warp 1   : gold-path numerator
//   warps 2-9: forward logsumexp as 8 chunk operators (5x5 log-semiring),
//              composed by warp 2 after a named barrier -> log_z
// Then: pointer-jumping backtrace (exact integer map composition), path
// write, and last-block deterministic loss reduction.
// ---------------------------------------------------------------------------
__global__ __launch_bounds__(320) void crf_kernel(
    const int*   __restrict__ labels,       // [B, S]
    const float* __restrict__ start_trans,  // [L]
    const float* __restrict__ end_trans,    // [L]
    const float* __restrict__ trans,        // [L, L] (prev, cur)
    const float* __restrict__ weights,      // [L]
    float*       __restrict__ d_out)        // [0]=loss, [1..]=paths
{
    __shared__ float         s_e[SEQ * LBL];        // emissions, this batch
    __shared__ unsigned char s_F[2][SEQ * LBL];     // map buffers (row 511 = identity)
    __shared__ float         s_M[8][25];            // chunk operators
    __shared__ float         s_logz, s_num;
    __shared__ int           s_last;

    int b = blockIdx.x;
    int tid = threadIdx.x, warp = tid >> 5, lane = tid & 31;

    const float* eb = g_emis + (size_t)b * SEQ * LBL;
    for (int i = tid; i < SEQ * LBL; i += 320) s_e[i] = eb[i];
    __syncthreads();

    if (warp == 0) {
        // ---------------- Viterbi (sequential, lanes 0-4) ----------------
        bool act = lane < LBL;
        int j = act ? lane : 0;
        float Tc0 = trans[0 * LBL + j];
        float Tc1 = trans[1 * LBL + j];
        float Tc2 = trans[2 * LBL + j];
        float Tc3 = trans[3 * LBL + j];
        float Tc4 = trans[4 * LBL + j];
        float en  = end_trans[j];

        float v = start_trans[j] + s_e[j];
        float e_next = s_e[LBL + j];

#pragma unroll 2
        for (int t = 1; t < SEQ; t++) {
            float e = e_next;
            if (t + 1 < SEQ) e_next = s_e[(t + 1) * LBL + j];

            float v0 = __shfl_sync(0xffffffffu, v, 0);
            float v1 = __shfl_sync(0xffffffffu, v, 1);
            float v2 = __shfl_sync(0xffffffffu, v, 2);
            float v3 = __shfl_sync(0xffffffffu, v, 3);
            float v4 = __shfl_sync(0xffffffffu, v, 4);

            float y0 = v0 + Tc0, y1 = v1 + Tc1, y2 = v2 + Tc2,
                  y3 = v3 + Tc3, y4 = v4 + Tc4;

            // value: balanced max tree (bit-exact, short latency)
            float b01 = fmaxf(y0, y1);
            float b23 = fmaxf(y2, y3);
            float b03 = fmaxf(b01, b23);
            float best = fmaxf(b03, y4);
            v = best + e;             // recurrence closes here

            // index: off the dependency chain; '>' keeps first-index-wins ties
            int i01 = (y1 > y0) ? 1 : 0;
            int i23 = (y3 > y2) ? 3 : 2;
            int i03 = (b23 > b01) ? i23 : i01;
            int idx = (y4 > b03) ? 4 : i03;
            if (act) s_F[0][(t - 1) * LBL + j] = (unsigned char)idx;
        }

        // last = argmax(v + end), first index wins ties
        float f = v + en;
        float f0 = __shfl_sync(0xffffffffu, f, 0);
        float f1 = __shfl_sync(0xffffffffu, f, 1);
        float f2 = __shfl_sync(0xffffffffu, f, 2);
        float f3 = __shfl_sync(0xffffffffu, f, 3);
        float f4 = __shfl_sync(0xffffffffu, f, 4);
        float fb = f0; int last = 0;
        if (f1 > fb) { fb = f1; last = 1; }
        if (f2 > fb) { fb = f2; last = 2; }
        if (f3 > fb) { fb = f3; last = 3; }
        if (f4 > fb) { fb = f4; last = 4; }
        if (lane == 0) s_last = last;
        if (act) s_F[0][(SEQ - 1) * LBL + j] = (unsigned char)j;  // identity row
    } else if (warp == 1) {
        // ---------------- numerator ----------------
        const int* lb = labels + b * SEQ;
        float acc = 0.f;
        for (int t = lane; t < SEQ; t += 32) {
            int l = lb[t];
            acc += weights[l] * s_e[t * LBL + l];
            if (t + 1 < SEQ) acc += trans[l * LBL + lb[t + 1]];
        }
#pragma unroll
        for (int off = 16; off; off >>= 1)
            acc += __shfl_down_sync(0xffffffffu, acc, off);
        if (lane == 0)
            s_num = acc + start_trans[lb[0]] + end_trans[lb[SEQ - 1]];
    } else {
        // ---------------- forward chunks (warps 2..9, chunk c = warp-2) ----
        int c = warp - 2;
        int t0 = (c == 0) ? 1 : 64 * c;
        int t1 = 64 * c + 63;
        bool act = lane < 25;
        int p = act ? lane : 0;
        int i5 = (p / 5) * 5;       // base lane of my source row
        int jj = p % 5;

        float Tr0 = trans[0 * LBL + jj];
        float Tr1 = trans[1 * LBL + jj];
        float Tr2 = trans[2 * LBL + jj];
        float Tr3 = trans[3 * LBL + jj];
        float Tr4 = trans[4 * LBL + jj];

        // M = A_{t0}
        float M = trans[(p / 5) * LBL + jj] + s_e[t0 * LBL + jj];

        for (int t = t0 + 1; t <= t1; t++) {
            float e = s_e[t * LBL + jj];
            float m0 = __shfl_sync(0xffffffffu, M, i5 + 0);
            float m1 = __shfl_sync(0xffffffffu, M, i5 + 1);
            float m2 = __shfl_sync(0xffffffffu, M, i5 + 2);
            float m3 = __shfl_sync(0xffffffffu, M, i5 + 3);
            float m4 = __shfl_sync(0xffffffffu, M, i5 + 4);
            float x0 = m0 + Tr0, x1 = m1 + Tr1, x2 = m2 + Tr2,
                  x3 = m3 + Tr3, x4 = m4 + Tr4;
            float mm = fmaxf(fmaxf(fmaxf(x0, x1), fmaxf(x2, x3)), x4);
            float me = mm + e;
            float s = (__expf(x0 - mm) + __expf(x1 - mm))
                    + (__expf(x2 - mm) + __expf(x3 - mm)) + __expf(x4 - mm);
            M = me + __logf(s);
        }
        if (act) s_M[c][p] = M;

        asm volatile("bar.sync 1, 256;" ::: "memory");  // warps 2..9 only

        if (warp == 2) {
            // compose: alpha0 (x) M_0 (x) ... (x) M_7, then log_z
            int j = (lane < LBL) ? lane : 0;
            float al = start_trans[j] + s_e[j];
#pragma unroll
            for (int cc = 0; cc < 8; cc++) {
                float a0 = __shfl_sync(0xffffffffu, al, 0);
                float a1 = __shfl_sync(0xffffffffu, al, 1);
                float a2 = __shfl_sync(0xffffffffu, al, 2);
                float a3 = __shfl_sync(0xffffffffu, al, 3);
                float a4 = __shfl_sync(0xffffffffu, al, 4);
                float x0 = a0 + s_M[cc][0 * 5 + j];
                float x1 = a1 + s_M[cc][1 * 5 + j];
                float x2 = a2 + s_M[cc][2 * 5 + j];
                float x3 = a3 + s_M[cc][3 * 5 + j];
                float x4 = a4 + s_M[cc][4 * 5 + j];
                float mm = fmaxf(fmaxf(fmaxf(x0, x1), fmaxf(x2, x3)), x4);
                float s = (__expf(x0 - mm) + __expf(x1 - mm))
                        + (__expf(x2 - mm) + __expf(x3 - mm)) + __expf(x4 - mm);
                al = mm + __logf(s);
            }
            float z = al + end_trans[j];
            float z0 = __shfl_sync(0xffffffffu, z, 0);
            float z1 = __shfl_sync(0xffffffffu, z, 1);
            float z2 = __shfl_sync(0xffffffffu, z, 2);
            float z3 = __shfl_sync(0xffffffffu, z, 3);
            float z4 = __shfl_sync(0xffffffffu, z, 4);
            float mz = fmaxf(fmaxf(fmaxf(z0, z1), fmaxf(z2, z3)), z4);
            float sz = __expf(z0 - mz) + __expf(z1 - mz) + __expf(z2 - mz)
                     + __expf(z3 - mz) + __expf(z4 - mz);
            if (lane == 0) s_logz = mz + __logf(sz);
        }
    }
    __syncthreads();

    // per-batch result + last-block deterministic loss reduction
    if (tid == 0) {
        g_res[b] = s_num - s_logz;
        __threadfence();
        int done = atomicAdd(&g_cnt, 1);
        if (done == BATCH - 1) {
            __threadfence();
            float a = 0.f;
            for (int q = 0; q < BATCH; q++) a += g_res[q];
            d_out[0] = -a / (float)(BATCH * SEQ);
            g_cnt = 0;  // reset for next graph replay
        }
    }

    // ---------------- pointer-jumping backtrace (exact) ----------------
    // s_F[src] row t in [0,510] = bp map (tag_{t+1} -> tag_t); row 511 = id.
    int src = 0;
    for (int d = 1; d < SEQ; d <<= 1) {
        int dst = src ^ 1;
        for (int t = tid; t < SEQ; t += 320) {
            unsigned char f[LBL];
            if (t + d <= SEQ - 1) {
#pragma unroll
                for (int q = 0; q < LBL; q++)
                    f[q] = s_F[src][t * LBL + s_F[src][(t + d) * LBL + q]];
            } else {
#pragma unroll
                for (int q = 0; q < LBL; q++)
                    f[q] = s_F[src][t * LBL + q];
            }
#pragma unroll
            for (int q = 0; q < LBL; q++)
                s_F[dst][t * LBL + q] = f[q];
        }
        __syncthreads();
        src ^= 1;
    }

    int last = s_last;
    float* out_paths = d_out + 1;
    for (int t = tid; t < SEQ; t += 320) {
        int tag = (t == SEQ - 1) ? last : (int)s_F[src][t * LBL + last];
        out_paths[(size_t)b * SEQ + t] = (float)tag;
    }
}

// ---------------------------------------------------------------------------
extern "C" void kernel_launch(void* const* d_in, const int* in_sizes, int n_in,
                              void* d_out, int out_size)
{
    const float* feats       = (const float*)d_in[0];  // [B,S,H]
    const int*   labels      = (const int*)  d_in[1];  // [B,S]
    // d_in[2] = mask: all-ones by construction, ignored
    const float* W_tag       = (const float*)d_in[3];  // [H,L]
    const float* b_tag       = (const float*)d_in[4];  // [L]
    const float* start_trans = (const float*)d_in[5];  // [L]
    const float* end_trans   = (const float*)d_in[6];  // [L]
    const float* trans       = (const float*)d_in[7];  // [L,L]
    const float* weights     = (const float*)d_in[8];  // [L]

    float* out = (float*)d_out;  // [0] = loss, [1..B*S] = paths

    emis_kernel<<<(BATCH * SEQ) / 64, 256>>>(feats, W_tag, b_tag);
    crf_kernel<<<BATCH, 320>>>(labels, start_trans, end_trans, trans, weights, out);
}

// round 5
// speedup vs baseline: 1.7044x; 1.0584x over previous
#include <cuda_runtime.h>

#define BATCH 64
#define SEQ   512
#define HID   1024
#define LBL   5
#define ESTR  8    // padded row stride (floats) for emissions / v-history

// Scratch (no allocations allowed -> __device__ globals)
__device__ float g_emis[BATCH * SEQ * ESTR];  // relu(feats@W+b), [B,S,8(5 used)]
__device__ float g_res[BATCH];                // per-batch (numerator - log_z)
__device__ int   g_cnt = 0;                   // last-block election counter

// ---------------------------------------------------------------------------
// Kernel 1: emissions = relu(feats @ W_tag + b_tag)
// 8 rows per warp, 256-thread blocks. Rows written with stride-8 padding so
// the CRF kernel can stage/read them with vector ops.
// ---------------------------------------------------------------------------
__global__ __launch_bounds__(256) void emis_kernel(
    const float* __restrict__ feats,   // [B*S, HID]
    const float* __restrict__ W,       // [HID, LBL]
    const float* __restrict__ bias)    // [LBL]
{
    __shared__ float sW[LBL * HID];    // transposed: sW[j*HID + k]
    int tid = threadIdx.x;
    for (int idx = tid; idx < LBL * HID; idx += 256) {
        int k = idx / LBL, j = idx - k * LBL;
        sW[j * HID + k] = W[idx];
    }
    __syncthreads();

    int warp = tid >> 5, lane = tid & 31;
    int row0 = blockIdx.x * 64 + warp * 8;   // 8 warps * 8 rows = 64 rows/block

    const float4* w4 = reinterpret_cast<const float4*>(sW);
    const float4* f4 = reinterpret_cast<const float4*>(feats) + (size_t)row0 * (HID / 4);

    float acc[8][LBL];
#pragma unroll
    for (int r = 0; r < 8; r++)
#pragma unroll
        for (int j = 0; j < LBL; j++) acc[r][j] = 0.f;

#pragma unroll
    for (int i = 0; i < HID / 4 / 32; i++) {
        int k4 = lane + 32 * i;
        float4 f[8];
#pragma unroll
        for (int r = 0; r < 8; r++) f[r] = f4[(size_t)r * (HID / 4) + k4];
#pragma unroll
        for (int j = 0; j < LBL; j++) {
            float4 w = w4[j * (HID / 4) + k4];
#pragma unroll
            for (int r = 0; r < 8; r++)
                acc[r][j] += f[r].x * w.x + f[r].y * w.y + f[r].z * w.z + f[r].w * w.w;
        }
    }

#pragma unroll
    for (int r = 0; r < 8; r++)
#pragma unroll
        for (int j = 0; j < LBL; j++)
#pragma unroll
            for (int off = 16; off; off >>= 1)
                acc[r][j] += __shfl_down_sync(0xffffffffu, acc[r][j], off);

    if (lane == 0) {
#pragma unroll
        for (int r = 0; r < 8; r++) {
            float* o = g_emis + (size_t)(row0 + r) * ESTR;
#pragma unroll
            for (int j = 0; j < LBL; j++)
                o[j] = fmaxf(acc[r][j] + bias[j], 0.f);
        }
    }
}

// ---------------------------------------------------------------------------
// Kernel 2: per-batch CRF. One block per batch, 10 warps:
//   warp 9   : Viterbi scan, SHUFFLE-FREE: all 5 states replicated in every
//              lane's registers; per step 25 FADD + 20 FMNMX + 5 FADD (exact:
//              max associative, single-add path sums). No per-step argmax;
//              v-history stored to smem (2 STS/step from lane 0).
//   warp 0   : gold-path numerator
//   warps 1-8: forward logsumexp chunk operators (as before), warp 1 composes
// After join: backpointers recomputed IN PARALLEL from v-history (exact same
// values + first-index-wins ties as reference), then pointer-jump backtrace.
// ---------------------------------------------------------------------------
__global__ __launch_bounds__(320) void crf_kernel(
    const int*   __restrict__ labels,       // [B, S]
    const float* __restrict__ start_trans,  // [L]
    const float* __restrict__ end_trans,    // [L]
    const float* __restrict__ trans,        // [L, L] (prev, cur)
    const float* __restrict__ weights,      // [L]
    float*       __restrict__ d_out)        // [0]=loss, [1..]=paths
{
    __shared__ float         s_e[SEQ * ESTR];       // emissions (stride 8)
    __shared__ float         s_v[SEQ * ESTR];       // viterbi value history
    __shared__ unsigned char s_F[2][SEQ * LBL];     // bp map buffers
    __shared__ float         s_M[8][25];            // forward chunk operators
    __shared__ float         s_T[25];               // trans staged
    __shared__ float         s_logz, s_num;
    __shared__ int           s_last;

    int b = blockIdx.x;
    int tid = threadIdx.x, warp = tid >> 5, lane = tid & 31;

    // Stage emissions (16KB, vectorized) + trans
    {
        const uint4* gsrc = reinterpret_cast<const uint4*>(g_emis + (size_t)b * SEQ * ESTR);
        uint4* sdst = reinterpret_cast<uint4*>(s_e);
        for (int i = tid; i < SEQ * ESTR / 4; i += 320) sdst[i] = gsrc[i];
        if (tid < 25) s_T[tid] = trans[tid];
    }
    __syncthreads();

    if (warp == 9) {
        // ---------------- Viterbi: replicated registers, no shuffles -------
        float T[LBL][LBL];
#pragma unroll
        for (int i = 0; i < LBL; i++)
#pragma unroll
            for (int j = 0; j < LBL; j++) T[i][j] = s_T[i * LBL + j];

        float v0 = start_trans[0] + s_e[0];
        float v1 = start_trans[1] + s_e[1];
        float v2 = start_trans[2] + s_e[2];
        float v3 = start_trans[3] + s_e[3];
        float v4 = start_trans[4] + s_e[4];
        if (lane == 0) {
            *reinterpret_cast<float4*>(&s_v[0]) = make_float4(v0, v1, v2, v3);
            s_v[4] = v4;
        }

        for (int t = 1; t < SEQ; t++) {
            float4 ea = *reinterpret_cast<const float4*>(&s_e[t * ESTR]);
            float  e4 = s_e[t * ESTR + 4];

            float n0 = fmaxf(fmaxf(fmaxf(v0 + T[0][0], v1 + T[1][0]),
                                   fmaxf(v2 + T[2][0], v3 + T[3][0])), v4 + T[4][0]) + ea.x;
            float n1 = fmaxf(fmaxf(fmaxf(v0 + T[0][1], v1 + T[1][1]),
                                   fmaxf(v2 + T[2][1], v3 + T[3][1])), v4 + T[4][1]) + ea.y;
            float n2 = fmaxf(fmaxf(fmaxf(v0 + T[0][2], v1 + T[1][2]),
                                   fmaxf(v2 + T[2][2], v3 + T[3][2])), v4 + T[4][2]) + ea.z;
            float n3 = fmaxf(fmaxf(fmaxf(v0 + T[0][3], v1 + T[1][3]),
                                   fmaxf(v2 + T[2][3], v3 + T[3][3])), v4 + T[4][3]) + ea.w;
            float n4 = fmaxf(fmaxf(fmaxf(v0 + T[0][4], v1 + T[1][4]),
                                   fmaxf(v2 + T[2][4], v3 + T[3][4])), v4 + T[4][4]) + e4;
            v0 = n0; v1 = n1; v2 = n2; v3 = n3; v4 = n4;

            if (lane == 0) {
                *reinterpret_cast<float4*>(&s_v[t * ESTR]) = make_float4(v0, v1, v2, v3);
                s_v[t * ESTR + 4] = v4;
            }
        }

        // last = argmax(v + end), first index wins ties (replicated, exact)
        float f0 = v0 + end_trans[0];
        float f1 = v1 + end_trans[1];
        float f2 = v2 + end_trans[2];
        float f3 = v3 + end_trans[3];
        float f4 = v4 + end_trans[4];
        float fb = f0; int last = 0;
        if (f1 > fb) { fb = f1; last = 1; }
        if (f2 > fb) { fb = f2; last = 2; }
        if (f3 > fb) { fb = f3; last = 3; }
        if (f4 > fb) { fb = f4; last = 4; }
        if (lane == 0) s_last = last;
    } else if (warp == 0) {
        // ---------------- numerator ----------------
        const int* lb = labels + b * SEQ;
        float acc = 0.f;
        for (int t = lane; t < SEQ; t += 32) {
            int l = lb[t];
            acc += weights[l] * s_e[t * ESTR + l];
            if (t + 1 < SEQ) acc += trans[l * LBL + lb[t + 1]];
        }
#pragma unroll
        for (int off = 16; off; off >>= 1)
            acc += __shfl_down_sync(0xffffffffu, acc, off);
        if (lane == 0)
            s_num = acc + start_trans[lb[0]] + end_trans[lb[SEQ - 1]];
    } else {
        // ---------------- forward chunks (warps 1..8, chunk c = warp-1) ----
        int c = warp - 1;
        int t0 = (c == 0) ? 1 : 64 * c;
        int t1 = 64 * c + 63;
        bool act = lane < 25;
        int p = act ? lane : 0;
        int i5 = (p / 5) * 5;       // base lane of my source row
        int jj = p % 5;

        float Tr0 = s_T[0 * LBL + jj];
        float Tr1 = s_T[1 * LBL + jj];
        float Tr2 = s_T[2 * LBL + jj];
        float Tr3 = s_T[3 * LBL + jj];
        float Tr4 = s_T[4 * LBL + jj];

        // M = A_{t0}
        float M = s_T[(p / 5) * LBL + jj] + s_e[t0 * ESTR + jj];

        for (int t = t0 + 1; t <= t1; t++) {
            float e = s_e[t * ESTR + jj];
            float m0 = __shfl_sync(0xffffffffu, M, i5 + 0);
            float m1 = __shfl_sync(0xffffffffu, M, i5 + 1);
            float m2 = __shfl_sync(0xffffffffu, M, i5 + 2);
            float m3 = __shfl_sync(0xffffffffu, M, i5 + 3);
            float m4 = __shfl_sync(0xffffffffu, M, i5 + 4);
            float x0 = m0 + Tr0, x1 = m1 + Tr1, x2 = m2 + Tr2,
                  x3 = m3 + Tr3, x4 = m4 + Tr4;
            float mm = fmaxf(fmaxf(fmaxf(x0, x1), fmaxf(x2, x3)), x4);
            float me = mm + e;
            float s = (__expf(x0 - mm) + __expf(x1 - mm))
                    + (__expf(x2 - mm) + __expf(x3 - mm)) + __expf(x4 - mm);
            M = me + __logf(s);
        }
        if (act) s_M[c][p] = M;

        asm volatile("bar.sync 1, 256;" ::: "memory");  // warps 1..8 only

        if (warp == 1) {
            // compose: alpha0 (x) M_0 (x) ... (x) M_7, then log_z
            int j = (lane < LBL) ? lane : 0;
            float al = start_trans[j] + s_e[j];
#pragma unroll
            for (int cc = 0; cc < 8; cc++) {
                float a0 = __shfl_sync(0xffffffffu, al, 0);
                float a1 = __shfl_sync(0xffffffffu, al, 1);
                float a2 = __shfl_sync(0xffffffffu, al, 2);
                float a3 = __shfl_sync(0xffffffffu, al, 3);
                float a4 = __shfl_sync(0xffffffffu, al, 4);
                float x0 = a0 + s_M[cc][0 * 5 + j];
                float x1 = a1 + s_M[cc][1 * 5 + j];
                float x2 = a2 + s_M[cc][2 * 5 + j];
                float x3 = a3 + s_M[cc][3 * 5 + j];
                float x4 = a4 + s_M[cc][4 * 5 + j];
                float mm = fmaxf(fmaxf(fmaxf(x0, x1), fmaxf(x2, x3)), x4);
                float s = (__expf(x0 - mm) + __expf(x1 - mm))
                        + (__expf(x2 - mm) + __expf(x3 - mm)) + __expf(x4 - mm);
                al = mm + __logf(s);
            }
            float z = al + end_trans[j];
            float z0 = __shfl_sync(0xffffffffu, z, 0);
            float z1 = __shfl_sync(0xffffffffu, z, 1);
            float z2 = __shfl_sync(0xffffffffu, z, 2);
            float z3 = __shfl_sync(0xffffffffu, z, 3);
            float z4 = __shfl_sync(0xffffffffu, z, 4);
            float mz = fmaxf(fmaxf(fmaxf(z0, z1), fmaxf(z2, z3)), z4);
            float sz = __expf(z0 - mz) + __expf(z1 - mz) + __expf(z2 - mz)
                     + __expf(z3 - mz) + __expf(z4 - mz);
            if (lane == 0) s_logz = mz + __logf(sz);
        }
    }
    __syncthreads();

    // per-batch result + last-block deterministic loss reduction
    if (tid == 0) {
        g_res[b] = s_num - s_logz;
        __threadfence();
        int done = atomicAdd(&g_cnt, 1);
        if (done == BATCH - 1) {
            __threadfence();
            float a = 0.f;
            for (int q = 0; q < BATCH; q++) a += g_res[q];
            d_out[0] = -a / (float)(BATCH * SEQ);
            g_cnt = 0;  // reset for next graph replay
        }
    }

    // ---------------- parallel backpointer recompute (exact) ----------------
    // bp row t (tag_{t+1} -> argmax_i v_t[i] + T[i][tag_{t+1}]), rows 0..510;
    // row 511 = identity. Same values + first-wins ties as sequential ref.
    for (int p = tid; p < SEQ * LBL; p += 320) {
        if (p < (SEQ - 1) * LBL) {
            int t = p / LBL, j = p - t * LBL;
            float4 va = *reinterpret_cast<const float4*>(&s_v[t * ESTR]);
            float  vb = s_v[t * ESTR + 4];
            float y0 = va.x + s_T[0 * LBL + j];
            float y1 = va.y + s_T[1 * LBL + j];
            float y2 = va.z + s_T[2 * LBL + j];
            float y3 = va.w + s_T[3 * LBL + j];
            float y4 = vb   + s_T[4 * LBL + j];
            float best = y0; int idx = 0;
            if (y1 > best) { best = y1; idx = 1; }
            if (y2 > best) { best = y2; idx = 2; }
            if (y3 > best) { best = y3; idx = 3; }
            if (y4 > best) { best = y4; idx = 4; }
            s_F[0][p] = (unsigned char)idx;
        } else {
            s_F[0][p] = (unsigned char)(p - (SEQ - 1) * LBL);  // identity row
        }
    }
    __syncthreads();

    // ---------------- pointer-jumping backtrace (exact) ----------------
    int src = 0;
    for (int d = 1; d < SEQ; d <<= 1) {
        int dst = src ^ 1;
        for (int t = tid; t < SEQ; t += 320) {
            unsigned char f[LBL];
            if (t + d <= SEQ - 1) {
#pragma unroll
                for (int q = 0; q < LBL; q++)
                    f[q] = s_F[src][t * LBL + s_F[src][(t + d) * LBL + q]];
            } else {
#pragma unroll
                for (int q = 0; q < LBL; q++)
                    f[q] = s_F[src][t * LBL + q];
            }
#pragma unroll
            for (int q = 0; q < LBL; q++)
                s_F[dst][t * LBL + q] = f[q];
        }
        __syncthreads();
        src ^= 1;
    }

    int last = s_last;
    float* out_paths = d_out + 1;
    for (int t = tid; t < SEQ; t += 320) {
        int tag = (t == SEQ - 1) ? last : (int)s_F[src][t * LBL + last];
        out_paths[(size_t)b * SEQ + t] = (float)tag;
    }
}

// ---------------------------------------------------------------------------
extern "C" void kernel_launch(void* const* d_in, const int* in_sizes, int n_in,
                              void* d_out, int out_size)
{
    const float* feats       = (const float*)d_in[0];  // [B,S,H]
    const int*   labels      = (const int*)  d_in[1];  // [B,S]
    // d_in[2] = mask: all-ones by construction, ignored
    const float* W_tag       = (const float*)d_in[3];  // [H,L]
    const float* b_tag       = (const float*)d_in[4];  // [L]
    const float* start_trans = (const float*)d_in[5];  // [L]
    const float* end_trans   = (const float*)d_in[6];  // [L]
    const float* trans       = (const float*)d_in[7];  // [L,L]
    const float* weights     = (const float*)d_in[8];  // [L]

    float* out = (float*)d_out;  // [0] = loss, [1..B*S] = paths

    emis_kernel<<<(BATCH * SEQ) / 64, 256>>>(feats, W_tag, b_tag);
    crf_kernel<<<BATCH, 320>>>(labels, start_trans, end_trans, trans, weights, out);
}